// round 5
// baseline (speedup 1.0000x reference)
#include <cuda_runtime.h>
#include <cuda_bf16.h>
#include <mma.h>
#include <cstdint>
#include <cstddef>

using namespace nvcuda;

#define T_SEQ 1024
#define B_SZ  64
// E = 256, H = 256, 4H = 1024

// ---------------- device-global scratch (no allocations) ----------------
__device__ float g_x   [(size_t)B_SZ * T_SEQ * 256];   // gathered embeddings
__device__ float g_xw1f[(size_t)B_SZ * T_SEQ * 1024];  // x @ fw1_Wi
__device__ float g_xw1b[(size_t)B_SZ * T_SEQ * 1024];  // x @ bw1_Wi
__device__ float g_xw2 [(size_t)B_SZ * T_SEQ * 1024];  // x1 @ fw2_Wi
__device__ float g_x1  [(size_t)B_SZ * T_SEQ * 512];   // layer-1 output [fwd|bwd]
__device__ float g_h2f [B_SZ * 256];                   // layer-2 fwd final h

// ---------------- helpers ----------------
__device__ __forceinline__ float sigf(float x) {
    return __fdividef(1.0f, 1.0f + __expf(-x));
}
__device__ __forceinline__ float tanhfast(float x) {
    float e = __expf(2.0f * x);
    return 1.0f - __fdividef(2.0f, e + 1.0f);
}
__device__ __forceinline__ uint32_t smem_u32(const void* p) {
    uint32_t a;
    asm("{ .reg .u64 t; cvta.to.shared.u64 t, %1; cvt.u32.u64 %0, t; }" : "=r"(a) : "l"(p));
    return a;
}

// ---------------- embedding gather ----------------
__global__ void gather_kernel(const int* __restrict__ tok, const float* __restrict__ emb) {
    size_t idx = (size_t)blockIdx.x * blockDim.x + threadIdx.x;  // 65536*64 float4
    int row = (int)(idx >> 6);
    int f   = (int)(idx & 63);
    int t   = __ldg(&tok[row]);
    ((float4*)g_x)[idx] = __ldg(&((const float4*)emb)[(size_t)t * 64 + f]);
}

// ---------------- bf16 WMMA GEMM: C[M,N] = A[M,K] @ B[K,N] ----------------
// CTA 128x128, 8 warps (2x4), warp 64x32, k-chunk 32, bf16 smem tiles.
#define GLDA 40
#define GLDB 136
__global__ __launch_bounds__(256) void gemm_bf16(const float* __restrict__ A,
                                                 const float* __restrict__ B,
                                                 float* __restrict__ C,
                                                 int N, int K) {
    __shared__ __nv_bfloat16 As[128 * GLDA];
    __shared__ __nv_bfloat16 Bs[32 * GLDB];
    const int tid = threadIdx.x;
    const int w   = tid >> 5;
    const int m0  = blockIdx.y * 128;
    const int n0  = blockIdx.x * 128;
    const int wm0 = (w >> 2) * 64;
    const int wn0 = (w & 3) * 32;

    wmma::fragment<wmma::accumulator, 16, 16, 16, float> c[4][2];
    #pragma unroll
    for (int i = 0; i < 4; i++)
        #pragma unroll
        for (int j = 0; j < 2; j++) wmma::fill_fragment(c[i][j], 0.0f);

    const int nkt = K >> 5;
    for (int kt = 0; kt < nkt; kt++) {
        // A tile 128x32 f32 -> bf16 (1024 float4, 4 per thread)
        #pragma unroll
        for (int p = 0; p < 4; p++) {
            int idx = tid + p * 256;
            int row = idx >> 3, c4 = idx & 7;
            float4 v = __ldg(&((const float4*)(A + (size_t)(m0 + row) * K + kt * 32))[c4]);
            __nv_bfloat162* dst = (__nv_bfloat162*)(As + row * GLDA + c4 * 4);
            dst[0] = __floats2bfloat162_rn(v.x, v.y);
            dst[1] = __floats2bfloat162_rn(v.z, v.w);
        }
        // B tile 32x128 f32 -> bf16
        #pragma unroll
        for (int p = 0; p < 4; p++) {
            int idx = tid + p * 256;
            int row = idx >> 5, c4 = idx & 31;
            float4 v = __ldg(&((const float4*)(B + (size_t)(kt * 32 + row) * N + n0))[c4]);
            __nv_bfloat162* dst = (__nv_bfloat162*)(Bs + row * GLDB + c4 * 4);
            dst[0] = __floats2bfloat162_rn(v.x, v.y);
            dst[1] = __floats2bfloat162_rn(v.z, v.w);
        }
        __syncthreads();
        #pragma unroll
        for (int kk = 0; kk < 32; kk += 16) {
            wmma::fragment<wmma::matrix_a, 16, 16, 16, __nv_bfloat16, wmma::row_major> a[4];
            wmma::fragment<wmma::matrix_b, 16, 16, 16, __nv_bfloat16, wmma::row_major> b[2];
            #pragma unroll
            for (int i = 0; i < 4; i++)
                wmma::load_matrix_sync(a[i], &As[(wm0 + i * 16) * GLDA + kk], GLDA);
            #pragma unroll
            for (int j = 0; j < 2; j++)
                wmma::load_matrix_sync(b[j], &Bs[kk * GLDB + wn0 + j * 16], GLDB);
            #pragma unroll
            for (int i = 0; i < 4; i++)
                #pragma unroll
                for (int j = 0; j < 2; j++)
                    wmma::mma_sync(c[i][j], a[i], b[j], c[i][j]);
        }
        __syncthreads();
    }
    #pragma unroll
    for (int i = 0; i < 4; i++)
        #pragma unroll
        for (int j = 0; j < 2; j++)
            wmma::store_matrix_sync(C + (size_t)(m0 + wm0 + i * 16) * N + n0 + wn0 + j * 16,
                                    c[i][j], N, wmma::mem_row_major);
}

// ---------------- persistent LSTM scan: cluster-8 + DSMEM h exchange ----------------
// Cluster of 8 CTAs = one batch group (8 rows). CTA rank owns 32 h-cols
// (=> 128 local z-cols, c = gate*32 + j). Wh slice (256x128) bf16 in SMEM.
// h lives ONLY in SMEM (double-buffered), broadcast to peers via st.shared::cluster.
#define WHS_LD 136
#define HS_LD  264
#define ZB_LD  132
#define WHS_BYTES (256 * WHS_LD * 2)                 // 69632
#define HS_OFF    WHS_BYTES
#define HSBUF     (16 * HS_LD)                        // elems per buffer
#define HS_BYTES  (2 * HSBUF * 2)                     // 16896
#define ZB_OFF    (HS_OFF + HS_BYTES)                 // 86528
#define ZB_BYTES  (16 * ZB_LD * 4)                    // 8448
#define SCAN_SMEM (ZB_OFF + ZB_BYTES)                 // 94976

__global__ __launch_bounds__(256, 1) void scan_kernel(
    const float* __restrict__ xw_f, const float* __restrict__ xw_b,
    const float* __restrict__ Wh_f, const float* __restrict__ Wh_b,
    const float* __restrict__ b_f,  const float* __restrict__ b_b,
    float* x1out, float* h2out) {
    extern __shared__ char sm[];
    __nv_bfloat16* Whs = (__nv_bfloat16*)sm;
    __nv_bfloat16* hs  = (__nv_bfloat16*)(sm + HS_OFF);
    float*         zb  = (float*)(sm + ZB_OFF);

    const int tid = threadIdx.x;
    const int w   = tid >> 5;
    const int dir = blockIdx.x >> 6;                  // scan2: always 0
    const int grp = (blockIdx.x >> 3) & 7;
    uint32_t rank;
    asm("mov.u32 %0, %%cluster_ctarank;" : "=r"(rank));
    const int r0  = grp * 8;
    const int hc0 = (int)rank * 32;

    const float* xw   = dir ? xw_b : xw_f;
    const float* Whg  = dir ? Wh_b : Wh_f;
    const float* bias = dir ? b_b  : b_f;

    // zero hs (both parity buffers; rows 8..15 stay zero -> M padded to 16)
    for (int i = tid; i < 2 * HSBUF; i += 256) hs[i] = __float2bfloat16(0.f);
    // stage Wh slice bf16: Whs[k][c], c = gate*32+j -> global col gate*256+hc0+j
    for (int i = tid; i < 256 * 128; i += 256) {
        int k = i >> 7, cc = i & 127;
        int gt = cc >> 5, j = cc & 31;
        Whs[k * WHS_LD + cc] =
            __float2bfloat16_rn(__ldg(&Whg[(size_t)k * 1024 + gt * 256 + hc0 + j]));
    }
    // gate role: row r (0..7), col j (0..31) -> global h index (r0+r, hc0+j)
    const int r = tid >> 5, j = tid & 31;
    const int colbase = hc0 + j;
    const float bi  = __ldg(&bias[0 * 256 + colbase]);
    const float bfv = __ldg(&bias[1 * 256 + colbase]);
    const float bgv = __ldg(&bias[2 * 256 + colbase]);
    const float bo  = __ldg(&bias[3 * 256 + colbase]);
    float c_state = 0.0f;
    const uint32_t hs_base = smem_u32(hs);
    __syncthreads();
    // all peers' hs zeroed before anyone's first remote write
    asm volatile("barrier.cluster.arrive.aligned;" ::: "memory");
    asm volatile("barrier.cluster.wait.aligned;"   ::: "memory");

    // prefetch xw for step 0
    float xwi, xwf, xwg, xwo;
    {
        int t0 = dir ? (T_SEQ - 1) : 0;
        const float* p = xw + ((size_t)(r0 + r) * T_SEQ + t0) * 1024 + colbase;
        xwi = __ldcs(p); xwf = __ldcs(p + 256); xwg = __ldcs(p + 512); xwo = __ldcs(p + 768);
    }

    for (int s = 0; s < T_SEQ; s++) {
        const int t_in = dir ? (T_SEQ - 1 - s) : s;
        // tensor-core z: warp w owns local cols n0..n0+15; K=256 over full h
        {
            const int n0 = w * 16;
            const __nv_bfloat16* hcur = hs + (s & 1) * HSBUF;
            wmma::fragment<wmma::accumulator, 16, 16, 16, float> acc0, acc1;
            wmma::fill_fragment(acc0, 0.0f);
            wmma::fill_fragment(acc1, 0.0f);
            #pragma unroll
            for (int kt = 0; kt < 16; kt += 2) {
                wmma::fragment<wmma::matrix_a, 16, 16, 16, __nv_bfloat16, wmma::row_major> a0, a1;
                wmma::fragment<wmma::matrix_b, 16, 16, 16, __nv_bfloat16, wmma::row_major> b0, b1;
                wmma::load_matrix_sync(a0, hcur + kt * 16, HS_LD);
                wmma::load_matrix_sync(b0, Whs + (kt * 16) * WHS_LD + n0, WHS_LD);
                wmma::mma_sync(acc0, a0, b0, acc0);
                wmma::load_matrix_sync(a1, hcur + (kt + 1) * 16, HS_LD);
                wmma::load_matrix_sync(b1, Whs + ((kt + 1) * 16) * WHS_LD + n0, WHS_LD);
                wmma::mma_sync(acc1, a1, b1, acc1);
            }
            #pragma unroll
            for (int e = 0; e < acc0.num_elements; e++) acc0.x[e] += acc1.x[e];
            wmma::store_matrix_sync(zb + n0, acc0, ZB_LD, wmma::mem_row_major);
        }
        __syncthreads();

        // gates (all 256 threads, one (row,col) each)
        {
            float zi = zb[r * ZB_LD +      j] + bi  + xwi;
            float zf = zb[r * ZB_LD + 32 + j] + bfv + xwf;
            float zg = zb[r * ZB_LD + 64 + j] + bgv + xwg;
            float zo = zb[r * ZB_LD + 96 + j] + bo  + xwo;
            c_state = sigf(zf) * c_state + sigf(zi) * tanhfast(zg);
            float hval = sigf(zo) * tanhfast(c_state);

            if (x1out)
                __stcg(x1out + ((size_t)(r0 + r) * T_SEQ + t_in) * 512 + dir * 256 + colbase, hval);
            if (h2out && s == T_SEQ - 1)
                h2out[(r0 + r) * 256 + colbase] = hval;

            if (s < T_SEQ - 1) {
                // broadcast h to all 8 cluster CTAs' hs[next parity]
                unsigned short hbits = __bfloat16_as_ushort(__float2bfloat16_rn(hval));
                uint32_t la = hs_base + (((s + 1) & 1) * HSBUF + r * HS_LD + colbase) * 2;
                #pragma unroll
                for (int p = 0; p < 8; p++) {
                    uint32_t ra;
                    asm("mapa.shared::cluster.u32 %0, %1, %2;" : "=r"(ra) : "r"(la), "r"(p));
                    asm volatile("st.shared::cluster.b16 [%0], %1;" :: "r"(ra), "h"(hbits) : "memory");
                }
                // prefetch xw for next step (DRAM latency hides under cluster barrier)
                int tn = dir ? (T_SEQ - 2 - s) : (s + 1);
                const float* p = xw + ((size_t)(r0 + r) * T_SEQ + tn) * 1024 + colbase;
                xwi = __ldcs(p); xwf = __ldcs(p + 256); xwg = __ldcs(p + 512); xwo = __ldcs(p + 768);
            }
        }
        if (s == T_SEQ - 1) break;
        // cluster barrier: release h writes, acquire peers' h
        asm volatile("barrier.cluster.arrive.aligned;" ::: "memory");
        asm volatile("barrier.cluster.wait.aligned;"   ::: "memory");
    }
}

// ---------------- head: layer-2 bwd single step + final dot + sigmoid ----------------
__global__ __launch_bounds__(256) void head_kernel(const float* __restrict__ Wi,
                                                   const float* __restrict__ b2,
                                                   const float* __restrict__ Wd,
                                                   const float* __restrict__ bd,
                                                   float* __restrict__ out) {
    __shared__ float xr[512];
    __shared__ float z[1024];
    __shared__ float red[8];
    const int b = blockIdx.x, tid = threadIdx.x;
    const float* xrow = g_x1 + ((size_t)b * T_SEQ + (T_SEQ - 1)) * 512;
    xr[tid] = xrow[tid];
    xr[tid + 256] = xrow[tid + 256];
    __syncthreads();
    const int c0 = tid * 4;
    float4 acc = *(const float4*)(b2 + c0);
    for (int k = 0; k < 512; k++) {
        float xv = xr[k];
        float4 wv = __ldg((const float4*)(Wi + (size_t)k * 1024 + c0));
        acc.x = fmaf(xv, wv.x, acc.x);
        acc.y = fmaf(xv, wv.y, acc.y);
        acc.z = fmaf(xv, wv.z, acc.z);
        acc.w = fmaf(xv, wv.w, acc.w);
    }
    *(float4*)(z + c0) = acc;
    __syncthreads();
    float zi = z[tid], zg = z[512 + tid], zo = z[768 + tid];
    float cst = sigf(zi) * tanhf(zg);           // c0 = 0 so forget term vanishes
    float h2b = sigf(zo) * tanhf(cst);
    float pl = g_h2f[b * 256 + tid] * __ldg(&Wd[tid]) + h2b * __ldg(&Wd[256 + tid]);
    #pragma unroll
    for (int off = 16; off; off >>= 1) pl += __shfl_down_sync(0xffffffffu, pl, off);
    if ((tid & 31) == 0) red[tid >> 5] = pl;
    __syncthreads();
    if (tid == 0) {
        float ssum = 0.f;
        #pragma unroll
        for (int q = 0; q < 8; q++) ssum += red[q];
        out[b] = sigf(ssum + bd[0]);
    }
}

// ---------------- launch ----------------
static void launch_scan(int nblocks,
                        const float* xw_f, const float* xw_b,
                        const float* Wh_f, const float* Wh_b,
                        const float* b_f,  const float* b_b,
                        float* x1out, float* h2out) {
    cudaLaunchConfig_t cfg = {};
    cfg.gridDim  = dim3((unsigned)nblocks, 1, 1);
    cfg.blockDim = dim3(256, 1, 1);
    cfg.dynamicSmemBytes = SCAN_SMEM;
    cfg.stream = 0;
    cudaLaunchAttribute at[1];
    at[0].id = cudaLaunchAttributeClusterDimension;
    at[0].val.clusterDim.x = 8; at[0].val.clusterDim.y = 1; at[0].val.clusterDim.z = 1;
    cfg.attrs = at; cfg.numAttrs = 1;
    cudaLaunchKernelEx(&cfg, scan_kernel, xw_f, xw_b, Wh_f, Wh_b, b_f, b_b, x1out, h2out);
}

extern "C" void kernel_launch(void* const* d_in, const int* in_sizes, int n_in,
                              void* d_out, int out_size) {
    const int*   tokens = (const int*)  d_in[0];
    const float* embed  = (const float*)d_in[1];
    const float* fw1_Wi = (const float*)d_in[2];
    const float* fw1_Wh = (const float*)d_in[3];
    const float* fw1_b  = (const float*)d_in[4];
    const float* bw1_Wi = (const float*)d_in[5];
    const float* bw1_Wh = (const float*)d_in[6];
    const float* bw1_b  = (const float*)d_in[7];
    const float* fw2_Wi = (const float*)d_in[8];
    const float* fw2_Wh = (const float*)d_in[9];
    const float* fw2_b  = (const float*)d_in[10];
    const float* bw2_Wi = (const float*)d_in[11];
    const float* bw2_b  = (const float*)d_in[13];
    const float* Wd     = (const float*)d_in[14];
    const float* bd     = (const float*)d_in[15];
    float* out = (float*)d_out;

    float *px, *pxw1f, *pxw1b, *pxw2, *px1, *ph2f;
    cudaGetSymbolAddress((void**)&px,    g_x);
    cudaGetSymbolAddress((void**)&pxw1f, g_xw1f);
    cudaGetSymbolAddress((void**)&pxw1b, g_xw1b);
    cudaGetSymbolAddress((void**)&pxw2,  g_xw2);
    cudaGetSymbolAddress((void**)&px1,   g_x1);
    cudaGetSymbolAddress((void**)&ph2f,  g_h2f);

    cudaFuncSetAttribute(scan_kernel, cudaFuncAttributeMaxDynamicSharedMemorySize, SCAN_SMEM);

    gather_kernel<<<16384, 256>>>(tokens, embed);
    gemm_bf16<<<dim3(8, 512), 256>>>(px, fw1_Wi, pxw1f, 1024, 256);
    gemm_bf16<<<dim3(8, 512), 256>>>(px, bw1_Wi, pxw1b, 1024, 256);
    launch_scan(128, pxw1f, pxw1b, fw1_Wh, bw1_Wh, fw1_b, bw1_b, px1, nullptr);
    gemm_bf16<<<dim3(8, 512), 256>>>(px1, fw2_Wi, pxw2, 1024, 512);
    launch_scan(64, pxw2, pxw2, fw2_Wh, fw2_Wh, fw2_b, fw2_b, nullptr, ph2f);
    head_kernel<<<64, 256>>>(bw2_Wi, bw2_b, Wd, bd, out);
}